// round 7
// baseline (speedup 1.0000x reference)
#include <cuda_runtime.h>
#include <math.h>

// ---------------- packed f32x2 helpers (PTX-only; ptxas won't auto-fuse) ----
__device__ __forceinline__ unsigned long long fma2(unsigned long long a,
                                                   unsigned long long b,
                                                   unsigned long long c) {
    unsigned long long d;
    asm("fma.rn.f32x2 %0, %1, %2, %3;" : "=l"(d) : "l"(a), "l"(b), "l"(c));
    return d;
}
__device__ __forceinline__ unsigned long long pk2(float lo, float hi) {
    unsigned long long r;
    asm("mov.b64 %0, {%1, %2};" : "=l"(r) : "f"(lo), "f"(hi));
    return r;
}
union F4U { float4 f; struct { unsigned long long lo, hi; } u; };

// U table: per row, 6 float4 = 12 duplicated float2 pairs
// layout per row: {S,S,1,1 | Ex0,Ex0,Ex1,Ex1 | Ex2,Ex2,E00,E00 |
//                  E11,E11,E22,E22 | 2E01,2E01,2E02,2E02 | 2E12,2E12,0,0}
#define NMAX 8192
__device__ float4 g_Upk[NMAX * 6];

// ---------------- U precompute kernel (fast intrinsics) ---------------------
__global__ void kent_precompute_U(const float* __restrict__ pred, int N) {
    const float LOG_TWO_PI = 1.8378770664093454836f;
    const float TWO_PI = 6.2831853071795864769f;
    const float EIGHT_PI = 25.132741228718345908f;
    const float EPS = 1e-6f;

    int i = blockIdx.x * blockDim.x + threadIdx.x;
    if (i >= N) return;
    const float* p = pred + (size_t)i * 5;

    float eta = p[0], alpha = p[1], psi = p[2];
    float kappa = p[3], beta = p[4];
    float sa, ca, se, ce, sp, cp;
    __sincosf(alpha, &sa, &ca);
    __sincosf(eta,   &se, &ce);
    __sincosf(psi,   &sp, &cp);
    float g1[3] = { ca,       sa * ce,                  sa * se };
    float g2[3] = { -cp * sa, cp * ca * ce - sp * se,   cp * ca * se + sp * ce };
    float g3[3] = { sp * sa,  -sp * ca * ce - cp * se,  -sp * ca * se + cp * ce };

    float km = kappa - 2.f * beta, kp = kappa + 2.f * beta;
    float lkm = __logf(km), lkp = __logf(kp);

    float c  = LOG_TWO_PI + kappa - 0.5f * __logf(km * kp + EPS);
    float ck = __logf(-TWO_PI * (4.f * beta * beta + kappa - kappa * kappa)) + kappa
             - (1.5f * lkm + 1.5f * lkp + EPS);
    float k2 = kappa * kappa, b2 = beta * beta;
    float poly = k2 * k2 - 2.f * kappa * k2 + (2.f - 8.f * b2) * k2
               + 8.f * b2 * kappa + 16.f * b2 * b2 + 4.f * b2;
    float ckk = __logf(TWO_PI * poly) + kappa - (2.5f * lkm + 2.5f * lkp + EPS);
    float cbeta = __logf(EIGHT_PI * kappa) + __logf(beta)
                - (1.5f * lkm + 1.5f * lkp + EPS);

    float l1  = __expf(ck  - c);
    float ekk = __expf(ckk - c);
    float eb  = __expf(cbeta - c);
    float l2 = 0.5f * (1.f - ekk + eb);
    float l3 = 0.5f * (1.f - ekk - eb);

    float E00 = l1*g1[0]*g1[0] + l2*g2[0]*g2[0] + l3*g3[0]*g3[0];
    float E11 = l1*g1[1]*g1[1] + l2*g2[1]*g2[1] + l3*g3[1]*g3[1];
    float E22 = l1*g1[2]*g1[2] + l2*g2[2]*g2[2] + l3*g3[2]*g3[2];
    float E01 = l1*g1[0]*g1[1] + l2*g2[0]*g2[1] + l3*g3[0]*g3[1];
    float E02 = l1*g1[0]*g1[2] + l2*g2[0]*g2[2] + l3*g3[0]*g3[2];
    float E12 = l1*g1[1]*g1[2] + l2*g2[1]*g2[2] + l3*g3[1]*g3[2];

    float Ex0 = l1 * g1[0], Ex1 = l1 * g1[1], Ex2 = l1 * g1[2];

    float qa2 = E00*g2[0]*g2[0] + E11*g2[1]*g2[1] + E22*g2[2]*g2[2]
              + 2.f*(E01*g2[0]*g2[1] + E02*g2[0]*g2[2] + E12*g2[1]*g2[2]);
    float qa3 = E00*g3[0]*g3[0] + E11*g3[1]*g3[1] + E22*g3[2]*g3[2]
              + 2.f*(E01*g3[0]*g3[1] + E02*g3[0]*g3[2] + E12*g3[1]*g3[2]);

    float kdot = kappa * (g1[0]*Ex0 + g1[1]*Ex1 + g1[2]*Ex2);
    float S = -c + kdot + beta * (qa2 - qa3);

    float4* U = g_Upk + (size_t)i * 6;
    U[0] = make_float4(S,        S,        1.f,      1.f);
    U[1] = make_float4(Ex0,      Ex0,      Ex1,      Ex1);
    U[2] = make_float4(Ex2,      Ex2,      E00,      E00);
    U[3] = make_float4(E11,      E11,      E22,      E22);
    U[4] = make_float4(2.f*E01,  2.f*E01,  2.f*E02,  2.f*E02);
    U[5] = make_float4(2.f*E12,  2.f*E12,  0.f,      0.f);
}

// ---------------- per-col V features (10 components; v0=1 folded out) -------
__device__ __forceinline__ void compute_V(float eta, float alpha, float psi,
                                          float kappa, float beta,
                                          float v[10]) {
    const float LOG_TWO_PI = 1.8378770664093454836f;
    const float EPS = 1e-6f;
    float sa, ca, se, ce, sp, cp;
    __sincosf(alpha, &sa, &ca);
    __sincosf(eta,   &se, &ce);
    __sincosf(psi,   &sp, &cp);
    float g1x = ca,       g1y = sa * ce,                 g1z = sa * se;
    float g2x = -cp * sa, g2y = cp * ca * ce - sp * se,  g2z = cp * ca * se + sp * ce;
    float g3x = sp * sa,  g3y = -sp * ca * ce - cp * se, g3z = -sp * ca * se + cp * ce;

    float km = kappa - 2.f * beta, kp = kappa + 2.f * beta;
    v[0] = LOG_TWO_PI + kappa - 0.5f * __logf(km * kp + EPS);   // c_b
    v[1] = -kappa * g1x;
    v[2] = -kappa * g1y;
    v[3] = -kappa * g1z;
    v[4] = beta * (g3x*g3x - g2x*g2x);
    v[5] = beta * (g3y*g3y - g2y*g2y);
    v[6] = beta * (g3z*g3z - g2z*g2z);
    v[7] = beta * (g3x*g3y - g2x*g2y);
    v[8] = beta * (g3x*g3z - g2x*g2z);
    v[9] = beta * (g3y*g3z - g2y*g2z);
}

// ---------------- main kernel: barrier-free, no shared ----------------------
// Block: 128 threads; tile = 8 rows x 512 cols; 4 cols/thread.
// U read per-row via uniform-address LDG.128 (L1-hit broadcast).
#define KLD_THREADS 128
#define KLD_ROWS    8

__global__ void __launch_bounds__(KLD_THREADS, 8)
kld_main(const float* __restrict__ targ, float* __restrict__ out,
         int N, int M) {
    int tid  = threadIdx.x;
    int col  = (blockIdx.x * KLD_THREADS + tid) * 4;
    int row0 = blockIdx.y * KLD_ROWS;
    int nrows = N - row0;
    if (nrows > KLD_ROWS) nrows = KLD_ROWS;

    bool vec = ((M & 3) == 0) && (col + 4 <= M);

    if (vec) {
        // --- V: 4 cols from raw targ params (5x LDG.128, 16B-aligned) ------
        float tp[20];
        const float4* src = reinterpret_cast<const float4*>(targ + (size_t)col * 5);
#pragma unroll
        for (int q = 0; q < 5; q++)
            *reinterpret_cast<float4*>(&tp[q * 4]) = src[q];

        unsigned long long vA[10], vB[10];
        {
            float v0[10], v1[10];
            compute_V(tp[0],  tp[1],  tp[2],  tp[3],  tp[4],  v0);
            compute_V(tp[5],  tp[6],  tp[7],  tp[8],  tp[9],  v1);
#pragma unroll
            for (int k = 0; k < 10; k++) vA[k] = pk2(v0[k], v1[k]);
            compute_V(tp[10], tp[11], tp[12], tp[13], tp[14], v0);
            compute_V(tp[15], tp[16], tp[17], tp[18], tp[19], v1);
#pragma unroll
            for (int k = 0; k < 10; k++) vB[k] = pk2(v0[k], v1[k]);
        }

        const float4* __restrict__ Ubase = g_Upk + (size_t)row0 * 6;
        if (nrows == KLD_ROWS) {
#pragma unroll
            for (int r = 0; r < KLD_ROWS; r++) {
                const float4* uj = Ubase + r * 6;
                F4U u0; u0.f = __ldg(uj + 0);            // {S,S,1,1}
                unsigned long long alo = fma2(u0.u.hi, vA[0], u0.u.lo);
                unsigned long long ahi = fma2(u0.u.hi, vB[0], u0.u.lo);
#pragma unroll
                for (int j = 1; j < 5; j++) {
                    F4U u; u.f = __ldg(uj + j);
                    alo = fma2(u.u.lo, vA[2*j-1], alo); ahi = fma2(u.u.lo, vB[2*j-1], ahi);
                    alo = fma2(u.u.hi, vA[2*j],   alo); ahi = fma2(u.u.hi, vB[2*j],   ahi);
                }
                F4U u5; u5.f = __ldg(uj + 5);            // {u10,u10,0,0}
                alo = fma2(u5.u.lo, vA[9], alo); ahi = fma2(u5.u.lo, vB[9], ahi);
                F4U res; res.u.lo = alo; res.u.hi = ahi;
                *reinterpret_cast<float4*>(out + (size_t)(row0 + r) * M + col) = res.f;
            }
        } else {
            for (int r = 0; r < nrows; r++) {
                const float4* uj = Ubase + r * 6;
                F4U u0; u0.f = __ldg(uj + 0);
                unsigned long long alo = fma2(u0.u.hi, vA[0], u0.u.lo);
                unsigned long long ahi = fma2(u0.u.hi, vB[0], u0.u.lo);
#pragma unroll
                for (int j = 1; j < 5; j++) {
                    F4U u; u.f = __ldg(uj + j);
                    alo = fma2(u.u.lo, vA[2*j-1], alo); ahi = fma2(u.u.lo, vB[2*j-1], ahi);
                    alo = fma2(u.u.hi, vA[2*j],   alo); ahi = fma2(u.u.hi, vB[2*j],   ahi);
                }
                F4U u5; u5.f = __ldg(uj + 5);
                alo = fma2(u5.u.lo, vA[9], alo); ahi = fma2(u5.u.lo, vB[9], ahi);
                F4U res; res.u.lo = alo; res.u.hi = ahi;
                *reinterpret_cast<float4*>(out + (size_t)(row0 + r) * M + col) = res.f;
            }
        }
    } else if (col < M) {
        // scalar tail path
        float vs[10];
        int ncols = M - col; if (ncols > 4) ncols = 4;
        for (int cc = 0; cc < ncols; cc++) {
            const float* p = targ + (size_t)(col + cc) * 5;
            compute_V(p[0], p[1], p[2], p[3], p[4], vs);
            for (int r = 0; r < nrows; r++) {
                const float4* uj = g_Upk + (size_t)(row0 + r) * 6;
                float4 u0 = __ldg(uj + 0);
                float4 u1 = __ldg(uj + 1);
                float4 u2 = __ldg(uj + 2);
                float4 u3 = __ldg(uj + 3);
                float4 u4 = __ldg(uj + 4);
                float4 u5 = __ldg(uj + 5);
                float acc = u0.x + vs[0];                 // S + c_b
                acc = fmaf(u1.x, vs[1], acc);
                acc = fmaf(u1.z, vs[2], acc);
                acc = fmaf(u2.x, vs[3], acc);
                acc = fmaf(u2.z, vs[4], acc);
                acc = fmaf(u3.x, vs[5], acc);
                acc = fmaf(u3.z, vs[6], acc);
                acc = fmaf(u4.x, vs[7], acc);
                acc = fmaf(u4.z, vs[8], acc);
                acc = fmaf(u5.x, vs[9], acc);
                out[(size_t)(row0 + r) * M + col + cc] = acc;
            }
        }
    }
}

extern "C" void kernel_launch(void* const* d_in, const int* in_sizes, int n_in,
                              void* d_out, int out_size) {
    const float* pred = (const float*)d_in[0];
    const float* targ = (const float*)d_in[1];
    float* out = (float*)d_out;
    int N = in_sizes[0] / 5;
    int M = in_sizes[1] / 5;

    kent_precompute_U<<<(N + 127) / 128, 128>>>(pred, N);

    dim3 grid((M + KLD_THREADS * 4 - 1) / (KLD_THREADS * 4),
              (N + KLD_ROWS - 1) / KLD_ROWS);
    kld_main<<<grid, KLD_THREADS>>>(targ, out, N, M);
}

// round 8
// speedup vs baseline: 1.1895x; 1.1895x over previous
#include <cuda_runtime.h>
#include <math.h>

// ---------------- packed f32x2 helpers (PTX-only; ptxas won't auto-fuse) ----
__device__ __forceinline__ unsigned long long fma2(unsigned long long a,
                                                   unsigned long long b,
                                                   unsigned long long c) {
    unsigned long long d;
    asm("fma.rn.f32x2 %0, %1, %2, %3;" : "=l"(d) : "l"(a), "l"(b), "l"(c));
    return d;
}
__device__ __forceinline__ unsigned long long pk2(float lo, float hi) {
    unsigned long long r;
    asm("mov.b64 %0, {%1, %2};" : "=l"(r) : "f"(lo), "f"(hi));
    return r;
}
union F4U { float4 f; struct { unsigned long long lo, hi; } u; };

// U table: per row, 6 float4 of duplicated pairs:
// {S,S,1,1 | Ex0,Ex0,Ex1,Ex1 | Ex2,Ex2,E00,E00 | E11,E11,E22,E22 |
//  2E01,2E01,2E02,2E02 | 2E12,2E12,0,0}
#define NMAX 8192
__device__ float4 g_Upk[NMAX * 6];

// ---------------- U precompute kernel (fast intrinsics, one wave) -----------
__global__ void kent_precompute_U(const float* __restrict__ pred, int N) {
    const float LOG_TWO_PI = 1.8378770664093454836f;
    const float TWO_PI = 6.2831853071795864769f;
    const float EIGHT_PI = 25.132741228718345908f;
    const float EPS = 1e-6f;

    int i = blockIdx.x * blockDim.x + threadIdx.x;
    if (i >= N) return;
    const float* p = pred + (size_t)i * 5;

    float eta = p[0], alpha = p[1], psi = p[2];
    float kappa = p[3], beta = p[4];
    float sa, ca, se, ce, sp, cp;
    __sincosf(alpha, &sa, &ca);
    __sincosf(eta,   &se, &ce);
    __sincosf(psi,   &sp, &cp);
    float g1[3] = { ca,       sa * ce,                  sa * se };
    float g2[3] = { -cp * sa, cp * ca * ce - sp * se,   cp * ca * se + sp * ce };
    float g3[3] = { sp * sa,  -sp * ca * ce - cp * se,  -sp * ca * se + cp * ce };

    float km = kappa - 2.f * beta, kp = kappa + 2.f * beta;
    float lkm = __logf(km), lkp = __logf(kp);

    float c  = LOG_TWO_PI + kappa - 0.5f * __logf(km * kp + EPS);
    float ck = __logf(-TWO_PI * (4.f * beta * beta + kappa - kappa * kappa)) + kappa
             - (1.5f * lkm + 1.5f * lkp + EPS);
    float k2 = kappa * kappa, b2 = beta * beta;
    float poly = k2 * k2 - 2.f * kappa * k2 + (2.f - 8.f * b2) * k2
               + 8.f * b2 * kappa + 16.f * b2 * b2 + 4.f * b2;
    float ckk = __logf(TWO_PI * poly) + kappa - (2.5f * lkm + 2.5f * lkp + EPS);
    float cbeta = __logf(EIGHT_PI * kappa) + __logf(beta)
                - (1.5f * lkm + 1.5f * lkp + EPS);

    float l1  = __expf(ck  - c);
    float ekk = __expf(ckk - c);
    float eb  = __expf(cbeta - c);
    float l2 = 0.5f * (1.f - ekk + eb);
    float l3 = 0.5f * (1.f - ekk - eb);

    float E00 = l1*g1[0]*g1[0] + l2*g2[0]*g2[0] + l3*g3[0]*g3[0];
    float E11 = l1*g1[1]*g1[1] + l2*g2[1]*g2[1] + l3*g3[1]*g3[1];
    float E22 = l1*g1[2]*g1[2] + l2*g2[2]*g2[2] + l3*g3[2]*g3[2];
    float E01 = l1*g1[0]*g1[1] + l2*g2[0]*g2[1] + l3*g3[0]*g3[1];
    float E02 = l1*g1[0]*g1[2] + l2*g2[0]*g2[2] + l3*g3[0]*g3[2];
    float E12 = l1*g1[1]*g1[2] + l2*g2[1]*g2[2] + l3*g3[1]*g3[2];

    float Ex0 = l1 * g1[0], Ex1 = l1 * g1[1], Ex2 = l1 * g1[2];

    float qa2 = E00*g2[0]*g2[0] + E11*g2[1]*g2[1] + E22*g2[2]*g2[2]
              + 2.f*(E01*g2[0]*g2[1] + E02*g2[0]*g2[2] + E12*g2[1]*g2[2]);
    float qa3 = E00*g3[0]*g3[0] + E11*g3[1]*g3[1] + E22*g3[2]*g3[2]
              + 2.f*(E01*g3[0]*g3[1] + E02*g3[0]*g3[2] + E12*g3[1]*g3[2]);

    float kdot = kappa * (g1[0]*Ex0 + g1[1]*Ex1 + g1[2]*Ex2);
    float S = -c + kdot + beta * (qa2 - qa3);

    float4* U = g_Upk + (size_t)i * 6;
    U[0] = make_float4(S,        S,        1.f,      1.f);
    U[1] = make_float4(Ex0,      Ex0,      Ex1,      Ex1);
    U[2] = make_float4(Ex2,      Ex2,      E00,      E00);
    U[3] = make_float4(E11,      E11,      E22,      E22);
    U[4] = make_float4(2.f*E01,  2.f*E01,  2.f*E02,  2.f*E02);
    U[5] = make_float4(2.f*E12,  2.f*E12,  0.f,      0.f);
}

// ---------------- per-col V features (10 components; v0=1 folded out) -------
__device__ __forceinline__ void compute_V(float eta, float alpha, float psi,
                                          float kappa, float beta,
                                          float v[10]) {
    const float LOG_TWO_PI = 1.8378770664093454836f;
    const float EPS = 1e-6f;
    float sa, ca, se, ce, sp, cp;
    __sincosf(alpha, &sa, &ca);
    __sincosf(eta,   &se, &ce);
    __sincosf(psi,   &sp, &cp);
    float g1x = ca,       g1y = sa * ce,                 g1z = sa * se;
    float g2x = -cp * sa, g2y = cp * ca * ce - sp * se,  g2z = cp * ca * se + sp * ce;
    float g3x = sp * sa,  g3y = -sp * ca * ce - cp * se, g3z = -sp * ca * se + cp * ce;

    float km = kappa - 2.f * beta, kp = kappa + 2.f * beta;
    v[0] = LOG_TWO_PI + kappa - 0.5f * __logf(km * kp + EPS);   // c_b
    v[1] = -kappa * g1x;
    v[2] = -kappa * g1y;
    v[3] = -kappa * g1z;
    v[4] = beta * (g3x*g3x - g2x*g2x);
    v[5] = beta * (g3y*g3y - g2y*g2y);
    v[6] = beta * (g3z*g3z - g2z*g2z);
    v[7] = beta * (g3x*g3y - g2x*g2y);
    v[8] = beta * (g3x*g3z - g2x*g2z);
    v[9] = beta * (g3y*g3z - g2y*g2z);
}

// ---------------- main kernel ------------------------------------------------
// R4 shape: 128 threads, 8 rows x 512 cols, 4 cols/thread, 1024 blocks.
// U tile staged: threads 0..47 LDG.128 -> (V compute hides latency) -> STS.
#define KLD_THREADS 128
#define KLD_ROWS    8

__global__ void __launch_bounds__(KLD_THREADS, 8)
kld_main(const float* __restrict__ targ, float* __restrict__ out,
         int N, int M) {
    int tid  = threadIdx.x;
    int col  = (blockIdx.x * KLD_THREADS + tid) * 4;
    int row0 = blockIdx.y * KLD_ROWS;
    int nrows = N - row0;
    if (nrows > KLD_ROWS) nrows = KLD_ROWS;

    __shared__ float4 sU4[KLD_ROWS * 6];

    // stage U tile: issue LDG now, consume after V compute
    float4 ureg;
    int nload = nrows * 6;
    if (tid < nload)
        ureg = g_Upk[(size_t)row0 * 6 + tid];

    bool vec = ((M & 3) == 0) && (col + 4 <= M);
    unsigned long long vA[10], vB[10];

    if (vec) {
        float tp[20];
        const float4* src = reinterpret_cast<const float4*>(targ + (size_t)col * 5);
#pragma unroll
        for (int q = 0; q < 5; q++)
            *reinterpret_cast<float4*>(&tp[q * 4]) = src[q];

        float v0[10], v1[10];
        compute_V(tp[0],  tp[1],  tp[2],  tp[3],  tp[4],  v0);
        compute_V(tp[5],  tp[6],  tp[7],  tp[8],  tp[9],  v1);
#pragma unroll
        for (int k = 0; k < 10; k++) vA[k] = pk2(v0[k], v1[k]);
        compute_V(tp[10], tp[11], tp[12], tp[13], tp[14], v0);
        compute_V(tp[15], tp[16], tp[17], tp[18], tp[19], v1);
#pragma unroll
        for (int k = 0; k < 10; k++) vB[k] = pk2(v0[k], v1[k]);
    }

    if (tid < nload)
        sU4[tid] = ureg;
    __syncthreads();

    if (vec) {
        if (nrows == KLD_ROWS) {
#pragma unroll
            for (int r = 0; r < KLD_ROWS; r++) {
                const float4* uj = sU4 + r * 6;
                F4U u0; u0.f = uj[0];                    // {S,S,1,1}
                unsigned long long alo = fma2(u0.u.hi, vA[0], u0.u.lo);
                unsigned long long ahi = fma2(u0.u.hi, vB[0], u0.u.lo);
#pragma unroll
                for (int j = 1; j < 5; j++) {
                    F4U u; u.f = uj[j];
                    alo = fma2(u.u.lo, vA[2*j-1], alo); ahi = fma2(u.u.lo, vB[2*j-1], ahi);
                    alo = fma2(u.u.hi, vA[2*j],   alo); ahi = fma2(u.u.hi, vB[2*j],   ahi);
                }
                F4U u5; u5.f = uj[5];                    // {u10,u10,0,0}
                alo = fma2(u5.u.lo, vA[9], alo); ahi = fma2(u5.u.lo, vB[9], ahi);
                F4U res; res.u.lo = alo; res.u.hi = ahi;
                *reinterpret_cast<float4*>(out + (size_t)(row0 + r) * M + col) = res.f;
            }
        } else {
            for (int r = 0; r < nrows; r++) {
                const float4* uj = sU4 + r * 6;
                F4U u0; u0.f = uj[0];
                unsigned long long alo = fma2(u0.u.hi, vA[0], u0.u.lo);
                unsigned long long ahi = fma2(u0.u.hi, vB[0], u0.u.lo);
#pragma unroll
                for (int j = 1; j < 5; j++) {
                    F4U u; u.f = uj[j];
                    alo = fma2(u.u.lo, vA[2*j-1], alo); ahi = fma2(u.u.lo, vB[2*j-1], ahi);
                    alo = fma2(u.u.hi, vA[2*j],   alo); ahi = fma2(u.u.hi, vB[2*j],   ahi);
                }
                F4U u5; u5.f = uj[5];
                alo = fma2(u5.u.lo, vA[9], alo); ahi = fma2(u5.u.lo, vB[9], ahi);
                F4U res; res.u.lo = alo; res.u.hi = ahi;
                *reinterpret_cast<float4*>(out + (size_t)(row0 + r) * M + col) = res.f;
            }
        }
    } else if (col < M) {
        // scalar tail path
        float vs[10];
        int ncols = M - col; if (ncols > 4) ncols = 4;
        for (int cc = 0; cc < ncols; cc++) {
            const float* p = targ + (size_t)(col + cc) * 5;
            compute_V(p[0], p[1], p[2], p[3], p[4], vs);
            for (int r = 0; r < nrows; r++) {
                const float4* uj = sU4 + r * 6;
                float acc = uj[0].x + vs[0];             // S + c_b
                acc = fmaf(uj[1].x, vs[1], acc);
                acc = fmaf(uj[1].z, vs[2], acc);
                acc = fmaf(uj[2].x, vs[3], acc);
                acc = fmaf(uj[2].z, vs[4], acc);
                acc = fmaf(uj[3].x, vs[5], acc);
                acc = fmaf(uj[3].z, vs[6], acc);
                acc = fmaf(uj[4].x, vs[7], acc);
                acc = fmaf(uj[4].z, vs[8], acc);
                acc = fmaf(uj[5].x, vs[9], acc);
                out[(size_t)(row0 + r) * M + col + cc] = acc;
            }
        }
    }
}

extern "C" void kernel_launch(void* const* d_in, const int* in_sizes, int n_in,
                              void* d_out, int out_size) {
    const float* pred = (const float*)d_in[0];
    const float* targ = (const float*)d_in[1];
    float* out = (float*)d_out;
    int N = in_sizes[0] / 5;
    int M = in_sizes[1] / 5;

    kent_precompute_U<<<(N + 63) / 64, 64>>>(pred, N);

    dim3 grid((M + KLD_THREADS * 4 - 1) / (KLD_THREADS * 4),
              (N + KLD_ROWS - 1) / KLD_ROWS);
    kld_main<<<grid, KLD_THREADS>>>(targ, out, N, M);
}

// round 9
// speedup vs baseline: 1.2143x; 1.0208x over previous
#include <cuda_runtime.h>
#include <math.h>

// ---------------- packed f32x2 helpers (PTX-only; ptxas won't auto-fuse) ----
__device__ __forceinline__ unsigned long long fma2(unsigned long long a,
                                                   unsigned long long b,
                                                   unsigned long long c) {
    unsigned long long d;
    asm("fma.rn.f32x2 %0, %1, %2, %3;" : "=l"(d) : "l"(a), "l"(b), "l"(c));
    return d;
}
__device__ __forceinline__ unsigned long long pk2(float lo, float hi) {
    unsigned long long r;
    asm("mov.b64 %0, {%1, %2};" : "=l"(r) : "f"(lo), "f"(hi));
    return r;
}
union F4U { float4 f; struct { unsigned long long lo, hi; } u; };
union F2U { float2 f; unsigned long long u; };

// ---------------- per-row U features (fast intrinsics; inline) --------------
__device__ __forceinline__ void compute_U(const float* __restrict__ p,
                                          float2* __restrict__ Urow) {
    const float LOG_TWO_PI = 1.8378770664093454836f;
    const float TWO_PI = 6.2831853071795864769f;
    const float EIGHT_PI = 25.132741228718345908f;
    const float EPS = 1e-6f;

    float eta = p[0], alpha = p[1], psi = p[2];
    float kappa = p[3], beta = p[4];
    float sa, ca, se, ce, sp, cp;
    __sincosf(alpha, &sa, &ca);
    __sincosf(eta,   &se, &ce);
    __sincosf(psi,   &sp, &cp);
    float g1[3] = { ca,       sa * ce,                  sa * se };
    float g2[3] = { -cp * sa, cp * ca * ce - sp * se,   cp * ca * se + sp * ce };
    float g3[3] = { sp * sa,  -sp * ca * ce - cp * se,  -sp * ca * se + cp * ce };

    float km = kappa - 2.f * beta, kp = kappa + 2.f * beta;
    float lkm = __logf(km), lkp = __logf(kp);

    float c  = LOG_TWO_PI + kappa - 0.5f * __logf(km * kp + EPS);
    float ck = __logf(-TWO_PI * (4.f * beta * beta + kappa - kappa * kappa)) + kappa
             - (1.5f * lkm + 1.5f * lkp + EPS);
    float k2 = kappa * kappa, b2 = beta * beta;
    float poly = k2 * k2 - 2.f * kappa * k2 + (2.f - 8.f * b2) * k2
               + 8.f * b2 * kappa + 16.f * b2 * b2 + 4.f * b2;
    float ckk = __logf(TWO_PI * poly) + kappa - (2.5f * lkm + 2.5f * lkp + EPS);
    float cbeta = __logf(EIGHT_PI * kappa) + __logf(beta)
                - (1.5f * lkm + 1.5f * lkp + EPS);

    float l1  = __expf(ck  - c);
    float ekk = __expf(ckk - c);
    float eb  = __expf(cbeta - c);
    float l2 = 0.5f * (1.f - ekk + eb);
    float l3 = 0.5f * (1.f - ekk - eb);

    float E00 = l1*g1[0]*g1[0] + l2*g2[0]*g2[0] + l3*g3[0]*g3[0];
    float E11 = l1*g1[1]*g1[1] + l2*g2[1]*g2[1] + l3*g3[1]*g3[1];
    float E22 = l1*g1[2]*g1[2] + l2*g2[2]*g2[2] + l3*g3[2]*g3[2];
    float E01 = l1*g1[0]*g1[1] + l2*g2[0]*g2[1] + l3*g3[0]*g3[1];
    float E02 = l1*g1[0]*g1[2] + l2*g2[0]*g2[2] + l3*g3[0]*g3[2];
    float E12 = l1*g1[1]*g1[2] + l2*g2[1]*g2[2] + l3*g3[1]*g3[2];

    float Ex0 = l1 * g1[0], Ex1 = l1 * g1[1], Ex2 = l1 * g1[2];

    float qa2 = E00*g2[0]*g2[0] + E11*g2[1]*g2[1] + E22*g2[2]*g2[2]
              + 2.f*(E01*g2[0]*g2[1] + E02*g2[0]*g2[2] + E12*g2[1]*g2[2]);
    float qa3 = E00*g3[0]*g3[0] + E11*g3[1]*g3[1] + E22*g3[2]*g3[2]
              + 2.f*(E01*g3[0]*g3[1] + E02*g3[0]*g3[2] + E12*g3[1]*g3[2]);

    float kdot = kappa * (g1[0]*Ex0 + g1[1]*Ex1 + g1[2]*Ex2);
    float S = -c + kdot + beta * (qa2 - qa3);

    float u[11] = { S, 1.f, Ex0, Ex1, Ex2, E00, E11, E22,
                    2.f*E01, 2.f*E02, 2.f*E12 };
#pragma unroll
    for (int k = 0; k < 11; k++) Urow[k] = make_float2(u[k], u[k]);
    Urow[11] = make_float2(0.f, 0.f);
}

// ---------------- per-col V features (10 components; v0=1 folded out) -------
__device__ __forceinline__ void compute_V(float eta, float alpha, float psi,
                                          float kappa, float beta,
                                          float v[10]) {
    const float LOG_TWO_PI = 1.8378770664093454836f;
    const float EPS = 1e-6f;
    float sa, ca, se, ce, sp, cp;
    __sincosf(alpha, &sa, &ca);
    __sincosf(eta,   &se, &ce);
    __sincosf(psi,   &sp, &cp);
    float g1x = ca,       g1y = sa * ce,                 g1z = sa * se;
    float g2x = -cp * sa, g2y = cp * ca * ce - sp * se,  g2z = cp * ca * se + sp * ce;
    float g3x = sp * sa,  g3y = -sp * ca * ce - cp * se, g3z = -sp * ca * se + cp * ce;

    float km = kappa - 2.f * beta, kp = kappa + 2.f * beta;
    v[0] = LOG_TWO_PI + kappa - 0.5f * __logf(km * kp + EPS);   // c_b
    v[1] = -kappa * g1x;
    v[2] = -kappa * g1y;
    v[3] = -kappa * g1z;
    v[4] = beta * (g3x*g3x - g2x*g2x);
    v[5] = beta * (g3y*g3y - g2y*g2y);
    v[6] = beta * (g3z*g3z - g2z*g2z);
    v[7] = beta * (g3x*g3y - g2x*g2y);
    v[8] = beta * (g3x*g3z - g2x*g2z);
    v[9] = beta * (g3y*g3z - g2y*g2z);
}

// one 2-column pass over the 8-row tile; v = packed {col_a, col_b} features
__device__ __forceinline__ void row_pass(const float2 (*sU)[12],
                                         const unsigned long long* __restrict__ v,
                                         float* __restrict__ out,
                                         size_t row0, int nrows, int M, int col) {
#pragma unroll
    for (int r = 0; r < 8; r++) {
        if (r >= nrows) break;
        const float4* uj = reinterpret_cast<const float4*>(sU[r]);
        F4U u0; u0.f = uj[0];                    // {S,S,1,1}
        unsigned long long acc = fma2(u0.u.hi, v[0], u0.u.lo);   // S + c_b
#pragma unroll
        for (int j = 1; j < 5; j++) {
            F4U u; u.f = uj[j];                  // {u2j-1.., dup pairs}
            acc = fma2(u.u.lo, v[2*j-1], acc);
            acc = fma2(u.u.hi, v[2*j],   acc);
        }
        F4U u5; u5.f = uj[5];                    // {u10,u10,0,0}
        acc = fma2(u5.u.lo, v[9], acc);
        F2U res; res.u = acc;
        *reinterpret_cast<float2*>(out + (row0 + r) * M + col) = res.f;
    }
}

// ---------------- fused kernel ----------------------------------------------
// 128 threads, tile = 8 rows x 512 cols, 4 cols/thread processed as TWO
// 2-column passes so only one 20-reg packed-V set is live at a time
// -> <=51 regs -> 10 CTAs/SM.
#define KLD_THREADS 128
#define KLD_ROWS    8

__global__ void __launch_bounds__(KLD_THREADS, 10)
kld_fused(const float* __restrict__ pred, const float* __restrict__ targ,
          float* __restrict__ out, int N, int M) {
    int tid  = threadIdx.x;
    int col  = (blockIdx.x * KLD_THREADS + tid) * 4;
    int row0 = blockIdx.y * KLD_ROWS;
    int nrows = N - row0;
    if (nrows > KLD_ROWS) nrows = KLD_ROWS;

    __shared__ float2 sU[KLD_ROWS][12];

    // --- U: threads 0..nrows-1, one row each (fast-intrinsic) ---------------
    if (tid < nrows)
        compute_U(pred + (size_t)(row0 + tid) * 5, sU[tid]);

    bool vec = ((M & 3) == 0) && (col + 4 <= M);

    if (vec) {
        // ---- pass 1: cols {col, col+1} -------------------------------------
        unsigned long long vA[10];
        {
            const float* base = targ + (size_t)col * 5;     // 80B-aligned
            float4 t0 = *reinterpret_cast<const float4*>(base);      // 0..3
            float4 t1 = *reinterpret_cast<const float4*>(base + 4);  // 4..7
            float2 t2 = *reinterpret_cast<const float2*>(base + 8);  // 8..9
            float v0[10], v1[10];
            compute_V(t0.x, t0.y, t0.z, t0.w, t1.x, v0);
            compute_V(t1.y, t1.z, t1.w, t2.x, t2.y, v1);
#pragma unroll
            for (int k = 0; k < 10; k++) vA[k] = pk2(v0[k], v1[k]);
        }
        __syncthreads();
        row_pass(sU, vA, out, (size_t)row0, nrows, M, col);

        // ---- pass 2: cols {col+2, col+3} -----------------------------------
        unsigned long long vB[10];
        {
            const float* base = targ + (size_t)col * 5 + 10;  // 8B-aligned
            float2 s0 = *reinterpret_cast<const float2*>(base);      // 10..11
            float2 s1 = *reinterpret_cast<const float2*>(base + 2);  // 12..13
            float2 s2 = *reinterpret_cast<const float2*>(base + 4);  // 14..15
            float2 s3 = *reinterpret_cast<const float2*>(base + 6);  // 16..17
            float2 s4 = *reinterpret_cast<const float2*>(base + 8);  // 18..19
            float v0[10], v1[10];
            compute_V(s0.x, s0.y, s1.x, s1.y, s2.x, v0);
            compute_V(s2.y, s3.x, s3.y, s4.x, s4.y, v1);
#pragma unroll
            for (int k = 0; k < 10; k++) vB[k] = pk2(v0[k], v1[k]);
        }
        row_pass(sU, vB, out, (size_t)row0, nrows, M, col + 2);
    } else {
        __syncthreads();
        if (col < M) {
            float vs[10];
            int ncols = M - col; if (ncols > 4) ncols = 4;
            for (int cc = 0; cc < ncols; cc++) {
                const float* p = targ + (size_t)(col + cc) * 5;
                compute_V(p[0], p[1], p[2], p[3], p[4], vs);
                for (int r = 0; r < nrows; r++) {
                    float acc = sU[r][0].x + vs[0];          // S + c_b
#pragma unroll
                    for (int k = 0; k < 9; k++)
                        acc = fmaf(sU[r][k + 2].x, vs[k + 1], acc);
                    out[(size_t)(row0 + r) * M + col + cc] = acc;
                }
            }
        }
    }
}

extern "C" void kernel_launch(void* const* d_in, const int* in_sizes, int n_in,
                              void* d_out, int out_size) {
    const float* pred = (const float*)d_in[0];
    const float* targ = (const float*)d_in[1];
    float* out = (float*)d_out;
    int N = in_sizes[0] / 5;
    int M = in_sizes[1] / 5;

    dim3 grid((M + KLD_THREADS * 4 - 1) / (KLD_THREADS * 4),
              (N + KLD_ROWS - 1) / KLD_ROWS);
    kld_fused<<<grid, KLD_THREADS>>>(pred, targ, out, N, M);
}